// round 1
// baseline (speedup 1.0000x reference)
#include <cuda_runtime.h>

// Problem constants (fixed shapes for this problem).
static constexpr int B_    = 4096;
static constexpr int NPRE  = 16384;
static constexpr int NPOST = 16384;
static constexpr int R_    = 32;
static constexpr int SPLITK = 8;

// Scratch (no allocations allowed -> __device__ globals).
__device__ float g_Zpart[SPLITK * B_ * R_];  // 4 MB   partial Z per K-split, [split][b][r]
__device__ float g_Zt[R_ * B_];              // 512 KB Z transposed, [r][b]
__device__ float g_Ut[R_ * NPOST];           // 2 MB   U transposed, [r][n]

// ---------------------------------------------------------------------------
// Kernel A: Zpart[split] = S[:, ksplit] @ V[ksplit, :]
// Block tile: 128 rows x 32 r, 128 threads, micro-tile 8 rows x 4 r.
// ---------------------------------------------------------------------------
__global__ __launch_bounds__(128) void gemmA(const float* __restrict__ S,
                                             const float* __restrict__ V) {
    const int rowtile = blockIdx.x;          // 0..31
    const int split   = blockIdx.y;          // 0..7
    const int tid     = threadIdx.x;
    const int rg      = tid & 7;             // r-group (8 groups of 4)
    const int mg      = tid >> 3;            // row-group (16 groups of 8)
    const int rbase   = rg * 4;
    const int rowbase = mg * 8;

    __shared__ float sS[16][132];            // [k][row], pad 4 to break STS conflicts
    __shared__ float sV[16][32];             // [k][r]

    float acc[8][4];
#pragma unroll
    for (int i = 0; i < 8; i++)
#pragma unroll
        for (int j = 0; j < 4; j++) acc[i][j] = 0.f;

    const int row0 = rowtile * 128;
    const int k0   = split * (NPRE / SPLITK);
    const int kend = k0 + NPRE / SPLITK;

    for (int kb = k0; kb < kend; kb += 16) {
        // Stage S tile [128 rows][16 k] -> transposed sS[k][row]
#pragma unroll
        for (int i = 0; i < 4; i++) {
            int idx = tid + i * 128;         // 0..511
            int r   = idx >> 2;              // row 0..127
            int kv  = (idx & 3) * 4;         // k sub-offset 0,4,8,12
            float4 v = *reinterpret_cast<const float4*>(
                &S[(size_t)(row0 + r) * NPRE + kb + kv]);
            sS[kv + 0][r] = v.x;
            sS[kv + 1][r] = v.y;
            sS[kv + 2][r] = v.z;
            sS[kv + 3][r] = v.w;
        }
        // Stage V tile [16 k][32 r] (contiguous copy)
        {
            int k  = tid >> 3;               // 0..15
            int rv = (tid & 7) * 4;          // 0..28
            *reinterpret_cast<float4*>(&sV[k][rv]) =
                *reinterpret_cast<const float4*>(&V[(size_t)(kb + k) * R_ + rv]);
        }
        __syncthreads();

#pragma unroll
        for (int kk = 0; kk < 16; kk++) {
            float4 v4 = *reinterpret_cast<const float4*>(&sV[kk][rbase]);
            float4 sa = *reinterpret_cast<const float4*>(&sS[kk][rowbase]);
            float4 sb = *reinterpret_cast<const float4*>(&sS[kk][rowbase + 4]);
            float sv[8] = {sa.x, sa.y, sa.z, sa.w, sb.x, sb.y, sb.z, sb.w};
            float vv[4] = {v4.x, v4.y, v4.z, v4.w};
#pragma unroll
            for (int i = 0; i < 8; i++)
#pragma unroll
                for (int j = 0; j < 4; j++)
                    acc[i][j] = fmaf(sv[i], vv[j], acc[i][j]);
        }
        __syncthreads();
    }

    // Disjoint write of partials: g_Zpart[split][row][r]
    float* out = &g_Zpart[(size_t)split * B_ * R_];
#pragma unroll
    for (int i = 0; i < 8; i++) {
        *reinterpret_cast<float4*>(&out[(size_t)(row0 + rowbase + i) * R_ + rbase]) =
            make_float4(acc[i][0], acc[i][1], acc[i][2], acc[i][3]);
    }
}

// ---------------------------------------------------------------------------
// Reduce split-K partials and transpose: g_Zt[r][b] = sum_s Zpart[s][b][r]
// ---------------------------------------------------------------------------
__global__ void reduceZ() {
    int g = blockIdx.x * blockDim.x + threadIdx.x;  // 0..131071
    int r = g >> 12;                                // /4096
    int b = g & (B_ - 1);
    float s = 0.f;
#pragma unroll
    for (int sp = 0; sp < SPLITK; sp++)
        s += g_Zpart[(size_t)sp * B_ * R_ + (size_t)b * R_ + r];
    g_Zt[r * B_ + b] = s;
}

// ---------------------------------------------------------------------------
// Transpose U: g_Ut[r][n] = U[n][r]
// ---------------------------------------------------------------------------
__global__ void transU(const float* __restrict__ U) {
    int g = blockIdx.x * blockDim.x + threadIdx.x;  // 0..524287
    int r = g >> 14;                                // /16384
    int n = g & (NPOST - 1);
    g_Ut[g] = U[(size_t)n * R_ + r];
}

// ---------------------------------------------------------------------------
// Kernel B: Y[b][n] = sum_r Zt[r][b] * Ut[r][n]
// Block tile: 128 b x 128 n, 256 threads, 8x8 micro-tile as 2x2 blocks of 4x4.
// ---------------------------------------------------------------------------
__global__ __launch_bounds__(256) void gemmB(float* __restrict__ Y) {
    const int ntile = blockIdx.x;  // 0..127
    const int btile = blockIdx.y;  // 0..31
    const int tid   = threadIdx.x;
    const int tx    = tid & 15;
    const int ty    = tid >> 4;
    const int ca = tx * 4, cb = 64 + tx * 4;
    const int ra = ty * 4, rb = 64 + ty * 4;

    __shared__ float sZ[32][128];  // [r][b]
    __shared__ float sU[32][128];  // [r][n]

    const int b0 = btile * 128;
    const int n0 = ntile * 128;

    // Stage both tiles: contiguous 512B rows, STS.128 conflict-free.
#pragma unroll
    for (int i = 0; i < 4; i++) {
        int idx = tid + i * 256;    // 0..1023
        int r   = idx >> 5;         // 0..31
        int c   = (idx & 31) * 4;   // 0..124
        *reinterpret_cast<float4*>(&sZ[r][c]) =
            *reinterpret_cast<const float4*>(&g_Zt[r * B_ + b0 + c]);
        *reinterpret_cast<float4*>(&sU[r][c]) =
            *reinterpret_cast<const float4*>(&g_Ut[r * NPOST + n0 + c]);
    }
    __syncthreads();

    float acc[8][8];
#pragma unroll
    for (int i = 0; i < 8; i++)
#pragma unroll
        for (int j = 0; j < 8; j++) acc[i][j] = 0.f;

#pragma unroll 8
    for (int r = 0; r < 32; r++) {
        float4 z0 = *reinterpret_cast<const float4*>(&sZ[r][ra]);
        float4 z1 = *reinterpret_cast<const float4*>(&sZ[r][rb]);
        float4 u0 = *reinterpret_cast<const float4*>(&sU[r][ca]);
        float4 u1 = *reinterpret_cast<const float4*>(&sU[r][cb]);
        float zz[8] = {z0.x, z0.y, z0.z, z0.w, z1.x, z1.y, z1.z, z1.w};
        float uu[8] = {u0.x, u0.y, u0.z, u0.w, u1.x, u1.y, u1.z, u1.w};
#pragma unroll
        for (int i = 0; i < 8; i++)
#pragma unroll
            for (int j = 0; j < 8; j++)
                acc[i][j] = fmaf(zz[i], uu[j], acc[i][j]);
    }

    // Store 8 rows x (two float4 col chunks) each; lanes contiguous in n.
#pragma unroll
    for (int i = 0; i < 8; i++) {
        int row = b0 + ((i < 4) ? (ra + i) : (rb + i - 4));
        float* yrow = &Y[(size_t)row * NPOST + n0];
        *reinterpret_cast<float4*>(&yrow[ca]) =
            make_float4(acc[i][0], acc[i][1], acc[i][2], acc[i][3]);
        *reinterpret_cast<float4*>(&yrow[cb]) =
            make_float4(acc[i][4], acc[i][5], acc[i][6], acc[i][7]);
    }
}

// ---------------------------------------------------------------------------
// Entry point. Inputs (metadata order): spikes, U, V, mask_row_ptr,
// mask_col_idx, mask_values. Masks are unused (reference never applies them).
// ---------------------------------------------------------------------------
extern "C" void kernel_launch(void* const* d_in, const int* in_sizes, int n_in,
                              void* d_out, int out_size) {
    const float* spikes = (const float*)d_in[0];
    const float* U      = (const float*)d_in[1];
    const float* V      = (const float*)d_in[2];
    float* Y            = (float*)d_out;

    gemmA<<<dim3(B_ / 128, SPLITK), 128>>>(spikes, V);
    reduceZ<<<(B_ * R_) / 256, 256>>>();
    transU<<<(NPOST * R_) / 256, 256>>>(U);
    gemmB<<<dim3(NPOST / 128, B_ / 128), 256>>>(Y);
}

// round 2
// speedup vs baseline: 1.6156x; 1.6156x over previous
#include <cuda_runtime.h>

// Problem constants (fixed shapes for this problem).
static constexpr int B_    = 4096;
static constexpr int NPRE  = 16384;
static constexpr int NPOST = 16384;
static constexpr int R_    = 32;
static constexpr int SPLITK = 32;
static constexpr int KRANGE = NPRE / SPLITK;   // 512

// Scratch (no allocations allowed -> __device__ globals).
__device__ float g_Zpart[SPLITK * B_ * R_];  // 16 MB  partial Z per K-split, [split][b][r]
__device__ float g_Zt[R_ * B_];              // 512 KB Z transposed, [r][b]
__device__ float g_Ut[R_ * NPOST];           // 2 MB   U transposed, [r][n]

// ---------------------------------------------------------------------------
// Kernel A: Zpart[split] = S[:, ksplit] @ V[ksplit, :]
// Block tile: 128 rows x 32 r, 128 threads, micro-tile 8 rows x 4 r.
// Register double-buffer: prefetch next k-chunk's LDGs across the compute.
// ---------------------------------------------------------------------------
__global__ __launch_bounds__(128) void gemmA(const float* __restrict__ S,
                                             const float* __restrict__ V) {
    const int rowtile = blockIdx.x;          // 0..31
    const int split   = blockIdx.y;          // 0..31
    const int tid     = threadIdx.x;
    const int rg      = tid & 7;             // r-group (8 groups of 4)
    const int mg      = tid >> 3;            // row-group (16 groups of 8)
    const int rbase   = rg * 4;
    const int rowbase = mg * 8;

    __shared__ float sS[16][132];            // [k][row], pad 4 to decorrelate STS banks
    __shared__ float sV[16][32];             // [k][r]

    float acc[8][4];
#pragma unroll
    for (int i = 0; i < 8; i++)
#pragma unroll
        for (int j = 0; j < 4; j++) acc[i][j] = 0.f;

    const int row0 = rowtile * 128;
    const int k0   = split * KRANGE;
    const int kend = k0 + KRANGE;

    // Staging geometry (per thread): k sub-offset fixed, 4 rows stride 32.
    const int kv   = (tid & 3) * 4;          // 0,4,8,12
    const int srow = tid >> 2;               // 0..31; rows srow + 32*i
    const int vk   = tid >> 3;               // 0..15
    const int vr   = (tid & 7) * 4;          // 0..28

    float4 pS[4];
    float4 pV;
    // Initial prefetch for the first chunk.
#pragma unroll
    for (int i = 0; i < 4; i++)
        pS[i] = *reinterpret_cast<const float4*>(
            &S[(size_t)(row0 + srow + 32 * i) * NPRE + k0 + kv]);
    pV = *reinterpret_cast<const float4*>(&V[(size_t)(k0 + vk) * R_ + vr]);

    for (int kb = k0; kb < kend; kb += 16) {
        __syncthreads();   // previous compute done before overwriting smem
        // Commit prefetched registers to smem (transposed S).
#pragma unroll
        for (int i = 0; i < 4; i++) {
            int r = srow + 32 * i;
            sS[kv + 0][r] = pS[i].x;
            sS[kv + 1][r] = pS[i].y;
            sS[kv + 2][r] = pS[i].z;
            sS[kv + 3][r] = pS[i].w;
        }
        *reinterpret_cast<float4*>(&sV[vk][vr]) = pV;
        __syncthreads();

        // Prefetch next chunk while computing this one.
        const int kn = kb + 16;
        if (kn < kend) {
#pragma unroll
            for (int i = 0; i < 4; i++)
                pS[i] = *reinterpret_cast<const float4*>(
                    &S[(size_t)(row0 + srow + 32 * i) * NPRE + kn + kv]);
            pV = *reinterpret_cast<const float4*>(&V[(size_t)(kn + vk) * R_ + vr]);
        }

#pragma unroll
        for (int kk = 0; kk < 16; kk++) {
            float4 v4 = *reinterpret_cast<const float4*>(&sV[kk][rbase]);
            float4 sa = *reinterpret_cast<const float4*>(&sS[kk][rowbase]);
            float4 sb = *reinterpret_cast<const float4*>(&sS[kk][rowbase + 4]);
            float sv[8] = {sa.x, sa.y, sa.z, sa.w, sb.x, sb.y, sb.z, sb.w};
            float vv[4] = {v4.x, v4.y, v4.z, v4.w};
#pragma unroll
            for (int i = 0; i < 8; i++)
#pragma unroll
                for (int j = 0; j < 4; j++)
                    acc[i][j] = fmaf(sv[i], vv[j], acc[i][j]);
        }
    }

    // Disjoint write of partials: g_Zpart[split][row][r]
    float* out = &g_Zpart[(size_t)split * B_ * R_];
#pragma unroll
    for (int i = 0; i < 8; i++) {
        *reinterpret_cast<float4*>(&out[(size_t)(row0 + rowbase + i) * R_ + rbase]) =
            make_float4(acc[i][0], acc[i][1], acc[i][2], acc[i][3]);
    }
}

// ---------------------------------------------------------------------------
// Reduce split-K partials and transpose: g_Zt[r][b] = sum_s Zpart[s][b][r]
// Warp reads contiguous 128B per split (b fixed per warp, r = lane).
// ---------------------------------------------------------------------------
__global__ void reduceZ() {
    int g = blockIdx.x * blockDim.x + threadIdx.x;  // 0..131071
    int b = g >> 5;
    int r = g & 31;
    float s = 0.f;
#pragma unroll
    for (int sp = 0; sp < SPLITK; sp++)
        s += g_Zpart[(size_t)sp * B_ * R_ + (size_t)b * R_ + r];
    g_Zt[r * B_ + b] = s;
}

// ---------------------------------------------------------------------------
// Transpose U: g_Ut[r][n] = U[n][r]
// ---------------------------------------------------------------------------
__global__ void transU(const float* __restrict__ U) {
    int g = blockIdx.x * blockDim.x + threadIdx.x;  // 0..524287
    int r = g >> 14;                                // /16384
    int n = g & (NPOST - 1);
    g_Ut[g] = U[(size_t)n * R_ + r];
}

// ---------------------------------------------------------------------------
// Kernel B: Y[b][n] = sum_r Zt[r][b] * Ut[r][n]
// Block tile: 128 b x 64 n, 256 threads, micro-tile 8b x 4n (32 acc regs).
// Lower register pressure -> 3-4 resident blocks/SM to hide LDS/staging.
// ---------------------------------------------------------------------------
__global__ __launch_bounds__(256) void gemmB(float* __restrict__ Y) {
    const int ntile = blockIdx.x;  // 0..255
    const int btile = blockIdx.y;  // 0..31
    const int tid   = threadIdx.x;
    const int tx    = tid & 15;    // n-group
    const int ty    = tid >> 4;    // b-group
    const int nb    = tx * 4;
    const int bb    = ty * 8;

    __shared__ float sZ[32][128];  // [r][b]  16 KB
    __shared__ float sU[32][64];   // [r][n]   8 KB

    const int b0 = btile * 128;
    const int n0 = ntile * 64;

    // Stage tiles: contiguous float4 rows, conflict-free.
#pragma unroll
    for (int i = 0; i < 4; i++) {
        int idx = tid + i * 256;    // 0..1023
        int r   = idx >> 5;         // 0..31
        int c   = (idx & 31) * 4;   // 0..124
        *reinterpret_cast<float4*>(&sZ[r][c]) =
            *reinterpret_cast<const float4*>(&g_Zt[r * B_ + b0 + c]);
    }
#pragma unroll
    for (int i = 0; i < 2; i++) {
        int idx = tid + i * 256;    // 0..511
        int r   = idx >> 4;         // 0..31
        int c   = (idx & 15) * 4;   // 0..60
        *reinterpret_cast<float4*>(&sU[r][c]) =
            *reinterpret_cast<const float4*>(&g_Ut[r * NPOST + n0 + c]);
    }
    __syncthreads();

    float acc[8][4];
#pragma unroll
    for (int i = 0; i < 8; i++)
#pragma unroll
        for (int j = 0; j < 4; j++) acc[i][j] = 0.f;

#pragma unroll
    for (int r = 0; r < 32; r++) {
        float4 u4 = *reinterpret_cast<const float4*>(&sU[r][nb]);
        float4 z0 = *reinterpret_cast<const float4*>(&sZ[r][bb]);
        float4 z1 = *reinterpret_cast<const float4*>(&sZ[r][bb + 4]);
        float zz[8] = {z0.x, z0.y, z0.z, z0.w, z1.x, z1.y, z1.z, z1.w};
        float uu[4] = {u4.x, u4.y, u4.z, u4.w};
#pragma unroll
        for (int i = 0; i < 8; i++)
#pragma unroll
            for (int j = 0; j < 4; j++)
                acc[i][j] = fmaf(zz[i], uu[j], acc[i][j]);
    }

    // Store: 8 rows x one float4 each; 16 lanes contiguous in n per row.
#pragma unroll
    for (int i = 0; i < 8; i++) {
        *reinterpret_cast<float4*>(&Y[(size_t)(b0 + bb + i) * NPOST + n0 + nb]) =
            make_float4(acc[i][0], acc[i][1], acc[i][2], acc[i][3]);
    }
}

// ---------------------------------------------------------------------------
// Entry point. Inputs (metadata order): spikes, U, V, mask_row_ptr,
// mask_col_idx, mask_values. Masks are unused (reference never applies them).
// ---------------------------------------------------------------------------
extern "C" void kernel_launch(void* const* d_in, const int* in_sizes, int n_in,
                              void* d_out, int out_size) {
    const float* spikes = (const float*)d_in[0];
    const float* U      = (const float*)d_in[1];
    const float* V      = (const float*)d_in[2];
    float* Y            = (float*)d_out;

    gemmA<<<dim3(B_ / 128, SPLITK), 128>>>(spikes, V);
    reduceZ<<<(B_ * R_) / 256, 256>>>();
    transU<<<(NPOST * R_) / 256, 256>>>(U);
    gemmB<<<dim3(NPOST / 64, B_ / 128), 256>>>(Y);
}